// round 13
// baseline (speedup 1.0000x reference)
#include <cuda_runtime.h>

typedef unsigned long long u64;
typedef unsigned char u8;

// ---------------- packed f32x2 helpers ----------------
__device__ __forceinline__ u64 f2pack(float a, float b) {
    u64 r; asm("mov.b64 %0,{%1,%2};" : "=l"(r) : "f"(a), "f"(b)); return r;
}
__device__ __forceinline__ void f2unpack(u64 v, float& a, float& b) {
    asm("mov.b64 {%0,%1},%2;" : "=f"(a), "=f"(b) : "l"(v));
}
__device__ __forceinline__ u64 f2fma(u64 a, u64 b, u64 c) {
    u64 d; asm("fma.rn.f32x2 %0,%1,%2,%3;" : "=l"(d) : "l"(a), "l"(b), "l"(c)); return d;
}
// exact bit -> {0.0f, 1.0f} pair (bit0 = even t, bit1 = odd t)
__device__ __forceinline__ u64 spike_pair(unsigned b) {
    unsigned lo = (b & 1u) ? 0x3f800000u : 0u;
    unsigned hi = (b & 2u) ? 0x3f800000u : 0u;
    return ((u64)hi << 32) | (u64)lo;
}

// ---------------- LIF step ----------------
__device__ __forceinline__ float lif(float x, float& u, float& v, float& ps) {
    u = __fadd_rn(__fmul_rn(0.75f, u), __fmul_rn(64.0f, x));
    float vv = (ps > 0.0f) ? 0.0f : __fadd_rn(__fmul_rn(0.96875f, v), u);
    float s  = (vv >= 5120.0f) ? 1.0f : 0.0f;
    v  = (s > 0.0f) ? 0.0f : vv;
    ps = s;
    return s;
}

// ---------------- static scratch ----------------
__device__ u8  g_x0b[64 * 48 * 4 * 26 * 26];
__device__ u8  g_s2b[64 * 48 * 8 * 12 * 12];
__device__ u8  g_s4b[64 * 48 * 16 * 6 * 6];
__device__ u64 g_s1[64 * 48 * 8 * 24 * 24];
__device__ u64 g_s3[64 * 48 * 16 * 12 * 12];
__device__ u64 g_s5[64 * 48 * 32 * 6 * 6];
__device__ u64 g_s6[64 * 48 * 32 * 3 * 3];
__device__ u64 g_s7[64 * 48 * 512];
__device__ float g_w1g[288 * 512];
__device__ float g_dummy[1];

// ---------------- dummy (profiling alignment: makes conv1 land in ncu window) ----------------
__global__ void k_dummy(float* d) { d[0] = 0.0f; }

// ---------------- input transpose: [n][t] f32 -> bytes [p][n] ----------------
__global__ void k_transpose_in(const float* __restrict__ in, u8* __restrict__ out) {
    __shared__ float tile[128][33];
    const int N = 48 * 4 * 26 * 26;  // 129792
    int n0 = blockIdx.x * 32;
    int tx = threadIdx.x, ty = threadIdx.y;  // block (32,8)
#pragma unroll
    for (int rb = 0; rb < 4; rb++)
#pragma unroll
        for (int cb = 0; cb < 4; cb++)
            tile[32 * cb + tx][ty + 8 * rb] = in[(size_t)(n0 + ty + 8 * rb) * 128 + 32 * cb + tx];
    __syncthreads();
#pragma unroll
    for (int pb = 0; pb < 8; pb++) {
        int p = ty + 8 * pb;
        u8 bv = (tile[2 * p][tx] > 0.0f ? 1u : 0u) | (tile[2 * p + 1][tx] > 0.0f ? 2u : 0u);
        out[(size_t)p * N + n0 + tx] = bv;
    }
}

// ---------------- fc1 weight gather: wg[g*2048 + o*4 + c] = w[o][4g+c] ----------------
__global__ void k_prep_w1(const float* __restrict__ w, float* __restrict__ wg) {
    int e = blockIdx.x * 256 + threadIdx.x;
    if (e >= 288 * 512) return;
    int c = e & 3;
    int o = (e >> 2) & 511;
    int g = e >> 11;
    wg[e] = w[o * 288 + g * 4 + c];
}

// ------- conv wsum: byte-packed spikes, position-blocked strips, batch-ranged -------
template<int IC, int IH, int IW, int OC, int K, int PAD, int OCB, int PB, int BLK, int BN>
__global__ void __launch_bounds__(BLK) k_conv_wsum(const u8* __restrict__ sin,
                                                   const float* __restrict__ wsrc,
                                                   u64* __restrict__ wout,
                                                   int b0) {
    constexpr int OH = IH + 2 * PAD - K + 1;
    constexpr int OW = IW + 2 * PAD - K + 1;
    constexpr int NI = 48 * IC * IH * IW;   // bytes per pair-slice
    constexpr int NO = 48 * OC * OH * OW;
    constexpr int OG = OC / OCB, NW = IC * K * K;
    constexpr int GPR = OW / PB;
    constexpr int PG  = OH * GPR;
    constexpr int SL  = PB + K - 1;

    __shared__ __align__(16) u64 sw[NW * OC];   // [widx][oc], packed (w,w)
    for (int i = threadIdx.x; i < NW * OC; i += BLK) {
        int oc = i % OC, widx = i / OC;
        int kx = widx % K, ky = (widx / K) % K, ic = widx / (K * K);
        float wv = wsrc[(((oc * IC) + ic) * K + ky) * K + kx];
        sw[i] = f2pack(wv, wv);
    }
    __syncthreads();

    int gid = blockIdx.x * BLK + threadIdx.x;
    if (gid >= BN * OG * PG) return;
    int pg = gid % PG;
    int r  = gid / PG;
    int og = r % OG, b = b0 + r / OG;
    int p  = blockIdx.y;
    int oy = pg / GPR;
    int ox0 = (pg % GPR) * PB;
    int oc0 = og * OCB;

    const u8* ip = sin + (size_t)p * NI + b * IC * IH * IW;

    u64 acc[OCB][PB];
#pragma unroll
    for (int j = 0; j < OCB; j++)
#pragma unroll
        for (int q = 0; q < PB; q++) acc[j][q] = 0ull;

#pragma unroll 1
    for (int ic = 0; ic < IC; ic++) {
#pragma unroll
        for (int ky = 0; ky < K; ky++) {
            int iy = oy + ky - PAD;
            bool vy = ((unsigned)iy < (unsigned)IH);
            u64 strip[SL];
#pragma unroll
            for (int e = 0; e < SL; e++) {
                int ix = ox0 - PAD + e;
                unsigned bv = 0u;
                if (vy && ((unsigned)ix < (unsigned)IW))
                    bv = __ldg(ip + (ic * IH + iy) * IW + ix);
                strip[e] = spike_pair(bv);
            }
#pragma unroll
            for (int kx = 0; kx < K; kx++) {
                const ulonglong2* wp =
                    reinterpret_cast<const ulonglong2*>(sw + ((ic * K + ky) * K + kx) * OC + oc0);
#pragma unroll
                for (int jj = 0; jj < OCB / 2; jj++) {
                    ulonglong2 wpair = wp[jj];
#pragma unroll
                    for (int q = 0; q < PB; q++) {
                        acc[2 * jj][q]     = f2fma(strip[q + kx], wpair.x, acc[2 * jj][q]);
                        acc[2 * jj + 1][q] = f2fma(strip[q + kx], wpair.y, acc[2 * jj + 1][q]);
                    }
                }
            }
        }
    }
    size_t ob = (size_t)p * NO + (size_t)(b * OC + oc0) * (OH * OW) + oy * OW + ox0;
#pragma unroll
    for (int j = 0; j < OCB; j++) {
        ulonglong2* dst = reinterpret_cast<ulonglong2*>(wout + ob + (size_t)j * (OH * OW));
#pragma unroll
        for (int q = 0; q < PB / 2; q++)
            dst[q] = make_ulonglong2(acc[j][2 * q], acc[j][2 * q + 1]);
    }
}

// ------- fused scan: conv-LIF + delay + 2x2 sum-pool + pool-LIF + delay -------
// BYTES=true -> emit u8 spike-pair bytes; false -> emit u64 f32 pairs
// neuron-ranged: processes pooled neurons [n0, n0+NN)
template<int C, int IH, int IW, int BLK, bool BYTES>
__global__ void __launch_bounds__(BLK) k_scan_pool(const u64* __restrict__ wsum,
                                                   void* __restrict__ soutv,
                                                   int n0, int NN) {
    constexpr int B = 48, PH = IH / 2, PW = IW / 2;
    constexpr int NC = B * C * IH * IW;
    constexpr int NP = B * C * PH * PW;
    int n = n0 + blockIdx.x * BLK + threadIdx.x;
    if (n >= n0 + NN) return;
    int px = n % PW, py = (n / PW) % PH;
    int c = (n / (PW * PH)) % C, b = n / (PW * PH * C);
    int base = ((b * C + c) * IH + 2 * py) * IW + 2 * px;   // even -> 16B aligned

    float uc[4], vc[4], pc[4], cs[4];
#pragma unroll
    for (int j = 0; j < 4; j++) { uc[j] = 0.0f; vc[j] = 0.0f; pc[j] = 0.0f; cs[j] = 0.0f; }
    float up = 0.0f, vp = 0.0f, pp = 0.0f, cy = 0.0f;

    u8*  soutb = (u8*)soutv;
    u64* soutq = (u64*)soutv;

#pragma unroll 8
    for (int p = 0; p < 64; p++) {
        const u64* q = wsum + (size_t)p * NC + base;
        ulonglong2 lo = *reinterpret_cast<const ulonglong2*>(q);
        ulonglong2 hi = *reinterpret_cast<const ulonglong2*>(q + IW);
        float xa[4], xb[4];
        f2unpack(lo.x, xa[0], xb[0]); f2unpack(lo.y, xa[1], xb[1]);
        f2unpack(hi.x, xa[2], xb[2]); f2unpack(hi.y, xa[3], xb[3]);

        float sA = __fadd_rn(__fadd_rn(cs[0], cs[1]), __fadd_rn(cs[2], cs[3]));
        float spA = lif(__fmul_rn(88.0f, sA), up, vp, pp);
#pragma unroll
        for (int j = 0; j < 4; j++) cs[j] = lif(xa[j], uc[j], vc[j], pc[j]);

        float sB = __fadd_rn(__fadd_rn(cs[0], cs[1]), __fadd_rn(cs[2], cs[3]));
        float spB = lif(__fmul_rn(88.0f, sB), up, vp, pp);
#pragma unroll
        for (int j = 0; j < 4; j++) cs[j] = lif(xb[j], uc[j], vc[j], pc[j]);

        if (BYTES) {
            soutb[(size_t)p * NP + n] =
                (cy > 0.0f ? 1u : 0u) | (spA > 0.0f ? 2u : 0u);
        } else {
            soutq[(size_t)p * NP + n] = f2pack(cy, spA);
        }
        cy = spB;
    }
}

// ------- fc1 wsum: t-parallel GEMM, 128 thr x 4 outs x 8 batches -------
__global__ void __launch_bounds__(128) k_fc1_wsum(const u64* __restrict__ sin,
                                                  const float* __restrict__ w4g,
                                                  u64* __restrict__ wout) {
    __shared__ __align__(16) u64 sm[8 * 288];
    int p = blockIdx.y;
    int b0 = blockIdx.x * 8;
    int tid = threadIdx.x;
    {
        const ulonglong2* src = reinterpret_cast<const ulonglong2*>(sin + (size_t)p * 13824 + b0 * 288);
        ulonglong2* dst = reinterpret_cast<ulonglong2*>(sm);
        for (int i = tid; i < 8 * 288 / 2; i += 128) dst[i] = src[i];
    }
    __syncthreads();

    const float4* w4 = (const float4*)w4g;
    const ulonglong2* sm2 = reinterpret_cast<const ulonglong2*>(sm);
    u64 acc[4][8];
#pragma unroll
    for (int j = 0; j < 4; j++)
#pragma unroll
        for (int bb = 0; bb < 8; bb++) acc[j][bb] = 0ull;

#pragma unroll 2
    for (int g = 0; g < 72; g++) {
        u64 wx[4], wy[4], wz[4], ww[4];
#pragma unroll
        for (int j = 0; j < 4; j++) {
            float4 wv = w4[g * 512 + tid + 128 * j];
            wx[j] = f2pack(wv.x, wv.x); wy[j] = f2pack(wv.y, wv.y);
            wz[j] = f2pack(wv.z, wv.z); ww[j] = f2pack(wv.w, wv.w);
        }
#pragma unroll
        for (int bb = 0; bb < 8; bb++) {
            ulonglong2 s01 = sm2[bb * 144 + 2 * g];
            ulonglong2 s23 = sm2[bb * 144 + 2 * g + 1];
#pragma unroll
            for (int j = 0; j < 4; j++) {
                u64 a = acc[j][bb];
                a = f2fma(s01.x, wx[j], a);
                a = f2fma(s01.y, wy[j], a);
                a = f2fma(s23.x, wz[j], a);
                a = f2fma(s23.y, ww[j], a);
                acc[j][bb] = a;
            }
        }
    }
#pragma unroll
    for (int bb = 0; bb < 8; bb++)
#pragma unroll
        for (int j = 0; j < 4; j++)
            wout[(size_t)p * 24576 + (b0 + bb) * 512 + tid + 128 * j] = acc[j][bb];
}

// ------- fc2 fused: fc1-LIF (inline, ps = delayed spike) + fc2 dot + LIF -> out [B][2][T] -------
__global__ void __launch_bounds__(32) k_fc2(const u64* __restrict__ wsum,
                                            const float* __restrict__ w2,
                                            float* __restrict__ out) {
    int gid = blockIdx.x;          // 96 = 48 * 2
    int b = gid >> 1, o = gid & 1;
    int lane = threadIdx.x;        // 32
    float wr[16];
#pragma unroll
    for (int k = 0; k < 16; k++) wr[k] = w2[o * 512 + lane * 16 + k];

    float u1[16], v1[16], ps1[16];
#pragma unroll
    for (int k = 0; k < 16; k++) { u1[k] = 0.0f; v1[k] = 0.0f; ps1[k] = 0.0f; }

    if (lane == 0) out[b * 256 + o * 128] = 0.0f;
    float uo = 0.0f, vo = 0.0f, pso = 0.0f;

    for (int p = 0; p < 64; p++) {
        const u64* pp = wsum + (size_t)p * 24576 + b * 512 + lane * 16;
        u64 xw[16];
#pragma unroll
        for (int k = 0; k < 16; k++) xw[k] = __ldg(pp + k);

        float a0 = 0.0f;
#pragma unroll
        for (int k = 0; k < 16; k++) a0 = __fmaf_rn(ps1[k], wr[k], a0);

        float a1 = 0.0f;
#pragma unroll
        for (int k = 0; k < 16; k++) {
            float x0, x1;
            f2unpack(xw[k], x0, x1);
            float s = lif(x0, u1[k], v1[k], ps1[k]);
            a1 = __fmaf_rn(s, wr[k], a1);
        }
#pragma unroll
        for (int k = 0; k < 16; k++) {
            float x0, x1;
            f2unpack(xw[k], x0, x1);
            lif(x1, u1[k], v1[k], ps1[k]);
        }

#pragma unroll
        for (int off = 16; off > 0; off >>= 1) {
            a0 += __shfl_xor_sync(0xFFFFFFFFu, a0, off);
            a1 += __shfl_xor_sync(0xFFFFFFFFu, a1, off);
        }
        float s0 = lif(a0, uo, vo, pso);
        float s1 = lif(a1, uo, vo, pso);
        if (lane == 0) {
            out[b * 256 + o * 128 + 2 * p + 1] = s0;
            if (2 * p + 2 < 128) out[b * 256 + o * 128 + 2 * p + 2] = s1;
        }
    }
}

// ---------------- launcher ----------------
extern "C" void kernel_launch(void* const* d_in, const int* in_sizes, int n_in,
                              void* d_out, int out_size) {
    (void)in_sizes; (void)n_in; (void)out_size;
    const float* spike_in = (const float*)d_in[0];
    const float* w1  = (const float*)d_in[1];
    const float* w2  = (const float*)d_in[2];
    const float* w3  = (const float*)d_in[3];
    const float* wf1 = (const float*)d_in[4];
    const float* wf2 = (const float*)d_in[5];
    float* out = (float*)d_out;

    void *px0, *ps1, *ps2, *ps3, *ps4, *ps5, *ps6, *ps7, *pw1g, *pdm;
    cudaGetSymbolAddress(&px0, g_x0b);
    cudaGetSymbolAddress(&ps1, g_s1);
    cudaGetSymbolAddress(&ps2, g_s2b);
    cudaGetSymbolAddress(&ps3, g_s3);
    cudaGetSymbolAddress(&ps4, g_s4b);
    cudaGetSymbolAddress(&ps5, g_s5);
    cudaGetSymbolAddress(&ps6, g_s6);
    cudaGetSymbolAddress(&ps7, g_s7);
    cudaGetSymbolAddress(&pw1g, g_w1g);
    cudaGetSymbolAddress(&pdm, g_dummy);

    dim3 tb(32, 8);
    k_transpose_in<<<129792 / 32, tb>>>(spike_in, (u8*)px0);          // launch 1
    k_prep_w1<<<(288 * 512 + 255) / 256, 256>>>(wf1, (float*)pw1g);   // launch 2
    k_dummy<<<1, 1>>>((float*)pdm);                                   // launch 3 (probe alignment)

    // conv1 half A (b 0..23): 3456 thr/slice -> 27 blocks x 64 slices    launch 4 (profiled)
    k_conv_wsum<4, 26, 26, 8, 5, 1, 8, 4, 128, 24><<<dim3(27, 64), 128>>>((const u8*)px0, w1, (u64*)ps1, 0);
    // scan1 half A (pooled neurons 0..27647)
    k_scan_pool<8, 24, 24, 256, true><<<108, 256>>>((const u64*)ps1, ps2, 0, 27648);
    // conv1 half B (b 24..47)
    k_conv_wsum<4, 26, 26, 8, 5, 1, 8, 4, 128, 24><<<dim3(27, 64), 128>>>((const u8*)px0, w1, (u64*)ps1, 24);
    // scan1 half B
    k_scan_pool<8, 24, 24, 256, true><<<108, 256>>>((const u64*)ps1, ps2, 27648, 27648);

    // conv2: 8x12x12 -> 16x12x12 (k3 pad1), OCB=8 (OG=2), PB=4
    k_conv_wsum<8, 12, 12, 16, 3, 1, 8, 4, 128, 48><<<dim3(27, 64), 128>>>((const u8*)ps2, w2, (u64*)ps3, 0);
    // scan2: conv2 LIF + pool 12->6 + LIF -> byte spikes (wsum2 fits L2)
    k_scan_pool<16, 12, 12, 128, true><<<216, 128>>>((const u64*)ps3, ps4, 0, 27648);
    // conv3: 16x6x6 -> 32x6x6 (k3 pad1), OCB=8 (OG=4), PB=2
    k_conv_wsum<16, 6, 6, 32, 3, 1, 8, 2, 128, 48><<<dim3(27, 64), 128>>>((const u8*)ps4, w3, (u64*)ps5, 0);
    // scan3: conv3 LIF + pool 6->3 + LIF -> u64 f32 pairs (fc1 input format)
    k_scan_pool<32, 6, 6, 64, false><<<216, 64>>>((const u64*)ps5, ps6, 0, 13824);
    // fc1 wsum GEMM
    k_fc1_wsum<<<dim3(6, 64), 128>>>((const u64*)ps6, (const float*)pw1g, (u64*)ps7);
    // fc2 fused (fc1 LIF inline) -> output [B][2][T]
    k_fc2<<<96, 32>>>((const u64*)ps7, wf2, out);
}

// round 15
// speedup vs baseline: 1.0489x; 1.0489x over previous
#include <cuda_runtime.h>

typedef unsigned long long u64;
typedef unsigned char u8;

// ---------------- packed f32x2 helpers ----------------
__device__ __forceinline__ u64 f2pack(float a, float b) {
    u64 r; asm("mov.b64 %0,{%1,%2};" : "=l"(r) : "f"(a), "f"(b)); return r;
}
__device__ __forceinline__ void f2unpack(u64 v, float& a, float& b) {
    asm("mov.b64 {%0,%1},%2;" : "=f"(a), "=f"(b) : "l"(v));
}
__device__ __forceinline__ u64 f2fma(u64 a, u64 b, u64 c) {
    u64 d; asm("fma.rn.f32x2 %0,%1,%2,%3;" : "=l"(d) : "l"(a), "l"(b), "l"(c)); return d;
}
// exact bit -> {0.0f, 1.0f} pair (bit0 = even t, bit1 = odd t)
__device__ __forceinline__ u64 spike_pair(unsigned b) {
    unsigned lo = (b & 1u) ? 0x3f800000u : 0u;
    unsigned hi = (b & 2u) ? 0x3f800000u : 0u;
    return ((u64)hi << 32) | (u64)lo;
}

// ---------------- LIF step ----------------
__device__ __forceinline__ float lif(float x, float& u, float& v, float& ps) {
    u = __fadd_rn(__fmul_rn(0.75f, u), __fmul_rn(64.0f, x));
    float vv = (ps > 0.0f) ? 0.0f : __fadd_rn(__fmul_rn(0.96875f, v), u);
    float s  = (vv >= 5120.0f) ? 1.0f : 0.0f;
    v  = (s > 0.0f) ? 0.0f : vv;
    ps = s;
    return s;
}

// ---------------- static scratch ----------------
__device__ u8  g_x0b[64 * 48 * 4 * 26 * 26];
__device__ u8  g_s2b[64 * 48 * 8 * 12 * 12];
__device__ u8  g_s4b[64 * 48 * 16 * 6 * 6];
__device__ u64 g_s1[64 * 48 * 8 * 24 * 24];
__device__ u64 g_s3[64 * 48 * 16 * 12 * 12];
__device__ u64 g_s5[64 * 48 * 32 * 6 * 6];
__device__ u64 g_s6[64 * 48 * 32 * 3 * 3];
__device__ u64 g_s7[64 * 48 * 512];
__device__ float g_w1g[288 * 512];
__device__ float g_dummy[1];

// ---------------- dummy (profiling alignment: conv1 lands in the ncu window) ----------------
__global__ void k_dummy(float* d) { d[0] = 0.0f; }

// ---------------- input transpose: [n][t] f32 -> bytes [p][n] ----------------
__global__ void k_transpose_in(const float* __restrict__ in, u8* __restrict__ out) {
    __shared__ float tile[128][33];
    const int N = 48 * 4 * 26 * 26;  // 129792
    int n0 = blockIdx.x * 32;
    int tx = threadIdx.x, ty = threadIdx.y;  // block (32,8)
#pragma unroll
    for (int rb = 0; rb < 4; rb++)
#pragma unroll
        for (int cb = 0; cb < 4; cb++)
            tile[32 * cb + tx][ty + 8 * rb] = in[(size_t)(n0 + ty + 8 * rb) * 128 + 32 * cb + tx];
    __syncthreads();
#pragma unroll
    for (int pb = 0; pb < 8; pb++) {
        int p = ty + 8 * pb;
        u8 bv = (tile[2 * p][tx] > 0.0f ? 1u : 0u) | (tile[2 * p + 1][tx] > 0.0f ? 2u : 0u);
        out[(size_t)p * N + n0 + tx] = bv;
    }
}

// ---------------- fc1 weight gather: wg[g*2048 + o*4 + c] = w[o][4g+c] ----------------
__global__ void k_prep_w1(const float* __restrict__ w, float* __restrict__ wg) {
    int e = blockIdx.x * 256 + threadIdx.x;
    if (e >= 288 * 512) return;
    int c = e & 3;
    int o = (e >> 2) & 511;
    int g = e >> 11;
    wg[e] = w[o * 288 + g * 4 + c];
}

// ------- conv wsum: byte-packed spikes, position-blocked strips -------
// __launch_bounds__(BLK, 4): cap at 128 regs -> 4 blocks (16 warps)/SM
template<int IC, int IH, int IW, int OC, int K, int PAD, int OCB, int PB, int BLK>
__global__ void __launch_bounds__(BLK, 4) k_conv_wsum(const u8* __restrict__ sin,
                                                      const float* __restrict__ wsrc,
                                                      u64* __restrict__ wout) {
    constexpr int OH = IH + 2 * PAD - K + 1;
    constexpr int OW = IW + 2 * PAD - K + 1;
    constexpr int NI = 48 * IC * IH * IW;   // bytes per pair-slice
    constexpr int NO = 48 * OC * OH * OW;
    constexpr int OG = OC / OCB, NW = IC * K * K;
    constexpr int GPR = OW / PB;
    constexpr int PG  = OH * GPR;
    constexpr int SL  = PB + K - 1;

    __shared__ __align__(16) u64 sw[NW * OC];   // [widx][oc], packed (w,w)
    for (int i = threadIdx.x; i < NW * OC; i += BLK) {
        int oc = i % OC, widx = i / OC;
        int kx = widx % K, ky = (widx / K) % K, ic = widx / (K * K);
        float wv = wsrc[(((oc * IC) + ic) * K + ky) * K + kx];
        sw[i] = f2pack(wv, wv);
    }
    __syncthreads();

    int gid = blockIdx.x * BLK + threadIdx.x;
    if (gid >= 48 * OG * PG) return;
    int pg = gid % PG;
    int r  = gid / PG;
    int og = r % OG, b = r / OG;
    int p  = blockIdx.y;
    int oy = pg / GPR;
    int ox0 = (pg % GPR) * PB;
    int oc0 = og * OCB;

    const u8* ip = sin + (size_t)p * NI + b * IC * IH * IW;

    u64 acc[OCB][PB];
#pragma unroll
    for (int j = 0; j < OCB; j++)
#pragma unroll
        for (int q = 0; q < PB; q++) acc[j][q] = 0ull;

#pragma unroll 1
    for (int ic = 0; ic < IC; ic++) {
#pragma unroll
        for (int ky = 0; ky < K; ky++) {
            int iy = oy + ky - PAD;
            bool vy = ((unsigned)iy < (unsigned)IH);
            u64 strip[SL];
#pragma unroll
            for (int e = 0; e < SL; e++) {
                int ix = ox0 - PAD + e;
                unsigned bv = 0u;
                if (vy && ((unsigned)ix < (unsigned)IW))
                    bv = __ldg(ip + (ic * IH + iy) * IW + ix);
                strip[e] = spike_pair(bv);
            }
#pragma unroll
            for (int kx = 0; kx < K; kx++) {
                const ulonglong2* wp =
                    reinterpret_cast<const ulonglong2*>(sw + ((ic * K + ky) * K + kx) * OC + oc0);
#pragma unroll
                for (int jj = 0; jj < OCB / 2; jj++) {
                    ulonglong2 wpair = wp[jj];
#pragma unroll
                    for (int q = 0; q < PB; q++) {
                        acc[2 * jj][q]     = f2fma(strip[q + kx], wpair.x, acc[2 * jj][q]);
                        acc[2 * jj + 1][q] = f2fma(strip[q + kx], wpair.y, acc[2 * jj + 1][q]);
                    }
                }
            }
        }
    }
    size_t ob = (size_t)p * NO + (size_t)(b * OC + oc0) * (OH * OW) + oy * OW + ox0;
#pragma unroll
    for (int j = 0; j < OCB; j++) {
        ulonglong2* dst = reinterpret_cast<ulonglong2*>(wout + ob + (size_t)j * (OH * OW));
#pragma unroll
        for (int q = 0; q < PB / 2; q++)
            dst[q] = make_ulonglong2(acc[j][2 * q], acc[j][2 * q + 1]);
    }
}

// ------- fused scan: conv-LIF + delay + 2x2 sum-pool + pool-LIF + delay -------
// BYTES=true -> emit u8 spike-pair bytes; false -> emit u64 f32 pairs
template<int C, int IH, int IW, int BLK, bool BYTES>
__global__ void __launch_bounds__(BLK) k_scan_pool(const u64* __restrict__ wsum,
                                                   void* __restrict__ soutv) {
    constexpr int B = 48, PH = IH / 2, PW = IW / 2;
    constexpr int NC = B * C * IH * IW;
    constexpr int NP = B * C * PH * PW;
    int n = blockIdx.x * BLK + threadIdx.x;
    if (n >= NP) return;
    int px = n % PW, py = (n / PW) % PH;
    int c = (n / (PW * PH)) % C, b = n / (PW * PH * C);
    int base = ((b * C + c) * IH + 2 * py) * IW + 2 * px;   // even -> 16B aligned

    float uc[4], vc[4], pc[4], cs[4];
#pragma unroll
    for (int j = 0; j < 4; j++) { uc[j] = 0.0f; vc[j] = 0.0f; pc[j] = 0.0f; cs[j] = 0.0f; }
    float up = 0.0f, vp = 0.0f, pp = 0.0f, cy = 0.0f;

    u8*  soutb = (u8*)soutv;
    u64* soutq = (u64*)soutv;

#pragma unroll 8
    for (int p = 0; p < 64; p++) {
        const u64* q = wsum + (size_t)p * NC + base;
        ulonglong2 lo = *reinterpret_cast<const ulonglong2*>(q);
        ulonglong2 hi = *reinterpret_cast<const ulonglong2*>(q + IW);
        float xa[4], xb[4];
        f2unpack(lo.x, xa[0], xb[0]); f2unpack(lo.y, xa[1], xb[1]);
        f2unpack(hi.x, xa[2], xb[2]); f2unpack(hi.y, xa[3], xb[3]);

        float sA = __fadd_rn(__fadd_rn(cs[0], cs[1]), __fadd_rn(cs[2], cs[3]));
        float spA = lif(__fmul_rn(88.0f, sA), up, vp, pp);
#pragma unroll
        for (int j = 0; j < 4; j++) cs[j] = lif(xa[j], uc[j], vc[j], pc[j]);

        float sB = __fadd_rn(__fadd_rn(cs[0], cs[1]), __fadd_rn(cs[2], cs[3]));
        float spB = lif(__fmul_rn(88.0f, sB), up, vp, pp);
#pragma unroll
        for (int j = 0; j < 4; j++) cs[j] = lif(xb[j], uc[j], vc[j], pc[j]);

        if (BYTES) {
            soutb[(size_t)p * NP + n] =
                (cy > 0.0f ? 1u : 0u) | (spA > 0.0f ? 2u : 0u);
        } else {
            soutq[(size_t)p * NP + n] = f2pack(cy, spA);
        }
        cy = spB;
    }
}

// ------- fc1 wsum: t-parallel GEMM, 128 thr x 4 outs x 8 batches -------
__global__ void __launch_bounds__(128) k_fc1_wsum(const u64* __restrict__ sin,
                                                  const float* __restrict__ w4g,
                                                  u64* __restrict__ wout) {
    __shared__ __align__(16) u64 sm[8 * 288];
    int p = blockIdx.y;
    int b0 = blockIdx.x * 8;
    int tid = threadIdx.x;
    {
        const ulonglong2* src = reinterpret_cast<const ulonglong2*>(sin + (size_t)p * 13824 + b0 * 288);
        ulonglong2* dst = reinterpret_cast<ulonglong2*>(sm);
        for (int i = tid; i < 8 * 288 / 2; i += 128) dst[i] = src[i];
    }
    __syncthreads();

    const float4* w4 = (const float4*)w4g;
    const ulonglong2* sm2 = reinterpret_cast<const ulonglong2*>(sm);
    u64 acc[4][8];
#pragma unroll
    for (int j = 0; j < 4; j++)
#pragma unroll
        for (int bb = 0; bb < 8; bb++) acc[j][bb] = 0ull;

#pragma unroll 2
    for (int g = 0; g < 72; g++) {
        u64 wx[4], wy[4], wz[4], ww[4];
#pragma unroll
        for (int j = 0; j < 4; j++) {
            float4 wv = w4[g * 512 + tid + 128 * j];
            wx[j] = f2pack(wv.x, wv.x); wy[j] = f2pack(wv.y, wv.y);
            wz[j] = f2pack(wv.z, wv.z); ww[j] = f2pack(wv.w, wv.w);
        }
#pragma unroll
        for (int bb = 0; bb < 8; bb++) {
            ulonglong2 s01 = sm2[bb * 144 + 2 * g];
            ulonglong2 s23 = sm2[bb * 144 + 2 * g + 1];
#pragma unroll
            for (int j = 0; j < 4; j++) {
                u64 a = acc[j][bb];
                a = f2fma(s01.x, wx[j], a);
                a = f2fma(s01.y, wy[j], a);
                a = f2fma(s23.x, wz[j], a);
                a = f2fma(s23.y, ww[j], a);
                acc[j][bb] = a;
            }
        }
    }
#pragma unroll
    for (int bb = 0; bb < 8; bb++)
#pragma unroll
        for (int j = 0; j < 4; j++)
            wout[(size_t)p * 24576 + (b0 + bb) * 512 + tid + 128 * j] = acc[j][bb];
}

// ------- fc2 fused: fc1-LIF (inline, ps = delayed spike) + fc2 dot + LIF -> out [B][2][T] -------
__global__ void __launch_bounds__(32) k_fc2(const u64* __restrict__ wsum,
                                            const float* __restrict__ w2,
                                            float* __restrict__ out) {
    int gid = blockIdx.x;          // 96 = 48 * 2
    int b = gid >> 1, o = gid & 1;
    int lane = threadIdx.x;        // 32
    float wr[16];
#pragma unroll
    for (int k = 0; k < 16; k++) wr[k] = w2[o * 512 + lane * 16 + k];

    float u1[16], v1[16], ps1[16];
#pragma unroll
    for (int k = 0; k < 16; k++) { u1[k] = 0.0f; v1[k] = 0.0f; ps1[k] = 0.0f; }

    if (lane == 0) out[b * 256 + o * 128] = 0.0f;
    float uo = 0.0f, vo = 0.0f, pso = 0.0f;

    for (int p = 0; p < 64; p++) {
        const u64* pp = wsum + (size_t)p * 24576 + b * 512 + lane * 16;
        u64 xw[16];
#pragma unroll
        for (int k = 0; k < 16; k++) xw[k] = __ldg(pp + k);

        float a0 = 0.0f;
#pragma unroll
        for (int k = 0; k < 16; k++) a0 = __fmaf_rn(ps1[k], wr[k], a0);

        float a1 = 0.0f;
#pragma unroll
        for (int k = 0; k < 16; k++) {
            float x0, x1;
            f2unpack(xw[k], x0, x1);
            float s = lif(x0, u1[k], v1[k], ps1[k]);
            a1 = __fmaf_rn(s, wr[k], a1);
        }
#pragma unroll
        for (int k = 0; k < 16; k++) {
            float x0, x1;
            f2unpack(xw[k], x0, x1);
            lif(x1, u1[k], v1[k], ps1[k]);
        }

#pragma unroll
        for (int off = 16; off > 0; off >>= 1) {
            a0 += __shfl_xor_sync(0xFFFFFFFFu, a0, off);
            a1 += __shfl_xor_sync(0xFFFFFFFFu, a1, off);
        }
        float s0 = lif(a0, uo, vo, pso);
        float s1 = lif(a1, uo, vo, pso);
        if (lane == 0) {
            out[b * 256 + o * 128 + 2 * p + 1] = s0;
            if (2 * p + 2 < 128) out[b * 256 + o * 128 + 2 * p + 2] = s1;
        }
    }
}

// ---------------- launcher ----------------
extern "C" void kernel_launch(void* const* d_in, const int* in_sizes, int n_in,
                              void* d_out, int out_size) {
    (void)in_sizes; (void)n_in; (void)out_size;
    const float* spike_in = (const float*)d_in[0];
    const float* w1  = (const float*)d_in[1];
    const float* w2  = (const float*)d_in[2];
    const float* w3  = (const float*)d_in[3];
    const float* wf1 = (const float*)d_in[4];
    const float* wf2 = (const float*)d_in[5];
    float* out = (float*)d_out;

    void *px0, *ps1, *ps2, *ps3, *ps4, *ps5, *ps6, *ps7, *pw1g, *pdm;
    cudaGetSymbolAddress(&px0, g_x0b);
    cudaGetSymbolAddress(&ps1, g_s1);
    cudaGetSymbolAddress(&ps2, g_s2b);
    cudaGetSymbolAddress(&ps3, g_s3);
    cudaGetSymbolAddress(&ps4, g_s4b);
    cudaGetSymbolAddress(&ps5, g_s5);
    cudaGetSymbolAddress(&ps6, g_s6);
    cudaGetSymbolAddress(&ps7, g_s7);
    cudaGetSymbolAddress(&pw1g, g_w1g);
    cudaGetSymbolAddress(&pdm, g_dummy);

    dim3 tb(32, 8);
    k_transpose_in<<<129792 / 32, tb>>>(spike_in, (u8*)px0);          // launch 1
    k_prep_w1<<<(288 * 512 + 255) / 256, 256>>>(wf1, (float*)pw1g);   // launch 2
    k_dummy<<<1, 1>>>((float*)pdm);                                   // launch 3 (probe alignment)

    // conv1: 4x26x26 -> 8x24x24 (k5 pad1), OCB=8 (OG=1), PB=4      launch 4 (profiled)
    k_conv_wsum<4, 26, 26, 8, 5, 1, 8, 4, 128><<<dim3(54, 64), 128>>>((const u8*)px0, w1, (u64*)ps1);
    // scan1: conv1 LIF + pool 24->12 + LIF -> byte spikes
    k_scan_pool<8, 24, 24, 256, true><<<216, 256>>>((const u64*)ps1, ps2);
    // conv2: 8x12x12 -> 16x12x12 (k3 pad1), OCB=8 (OG=2), PB=4
    k_conv_wsum<8, 12, 12, 16, 3, 1, 8, 4, 128><<<dim3(27, 64), 128>>>((const u8*)ps2, w2, (u64*)ps3);
    // scan2: conv2 LIF + pool 12->6 + LIF -> byte spikes
    k_scan_pool<16, 12, 12, 128, true><<<216, 128>>>((const u64*)ps3, ps4);
    // conv3: 16x6x6 -> 32x6x6 (k3 pad1), OCB=8 (OG=4), PB=2
    k_conv_wsum<16, 6, 6, 32, 3, 1, 8, 2, 128><<<dim3(27, 64), 128>>>((const u8*)ps4, w3, (u64*)ps5);
    // scan3: conv3 LIF + pool 6->3 + LIF -> u64 f32 pairs (fc1 input format)
    k_scan_pool<32, 6, 6, 64, false><<<216, 64>>>((const u64*)ps5, ps6);
    // fc1 wsum GEMM
    k_fc1_wsum<<<dim3(6, 64), 128>>>((const u64*)ps6, (const float*)pw1g, (u64*)ps7);
    // fc2 fused (fc1 LIF inline) -> output [B][2][T]
    k_fc2<<<96, 32>>>((const u64*)ps7, wf2, out);
}